// round 5
// baseline (speedup 1.0000x reference)
#include <cuda_runtime.h>
#include <cuda_bf16.h>
#include <cstdint>

#define NN 20000
#define EE 300000
#define HH 128
#define LL 8
#define PITCH 272   // smem row pitch bytes (136 bf16) — conflict-free ldmatrix

// 64-row-tile smem layout (bytes)
#define A_HI 0
#define A_LO 17408
#define B_HI 34816
#define B_LO 69632
#define SM_IDX 104448
#define SMEM_SZ 104960

// ============================ scratch globals ===============================
__device__ __align__(16) float g_x  [NN * HH];
__device__ __align__(16) float g_e  [EE * HH];
__device__ __align__(16) float g_xs [NN * HH];
__device__ __align__(16) float g_xd [NN * HH];
__device__ __align__(16) float g_agg[NN * HH];

// packed weights: per matrix [hi 128x128 | lo 128x128] bf16, TRANSPOSED
__device__ __align__(16) __nv_bfloat16 g_wsrc[LL * 32768];
__device__ __align__(16) __nv_bfloat16 g_wdst[LL * 32768];
__device__ __align__(16) __nv_bfloat16 g_we  [LL * 32768];
__device__ __align__(16) __nv_bfloat16 g_we2 [LL * 32768];
__device__ __align__(16) __nv_bfloat16 g_wnx [LL * 32768];
__device__ __align__(16) __nv_bfloat16 g_wna [LL * 32768];
__device__ __align__(16) __nv_bfloat16 g_wn2 [LL * 32768];
__device__ __align__(16) __nv_bfloat16 g_wne2[32768];
__device__ __align__(16) __nv_bfloat16 g_wee2[32768];

// ============================ helpers =======================================
__device__ __forceinline__ uint32_t smem_u32(const void* p) {
    uint32_t a;
    asm("{ .reg .u64 t; cvta.to.shared.u64 t, %1; cvt.u32.u64 %0, t; }"
        : "=r"(a) : "l"(p));
    return a;
}
__device__ __forceinline__ void ldsm4(uint32_t addr, uint32_t r[4]) {
    asm volatile("ldmatrix.sync.aligned.m8n8.x4.shared.b16 {%0,%1,%2,%3}, [%4];"
                 : "=r"(r[0]), "=r"(r[1]), "=r"(r[2]), "=r"(r[3]) : "r"(addr));
}
__device__ __forceinline__ void mma16816(float c[4], const uint32_t a[4],
                                         const uint32_t* b) {
    asm volatile("mma.sync.aligned.m16n8k16.row.col.f32.bf16.bf16.f32 "
                 "{%0,%1,%2,%3}, {%4,%5,%6,%7}, {%8,%9}, {%0,%1,%2,%3};"
                 : "+f"(c[0]), "+f"(c[1]), "+f"(c[2]), "+f"(c[3])
                 : "r"(a[0]), "r"(a[1]), "r"(a[2]), "r"(a[3]),
                   "r"(b[0]), "r"(b[1]));
}

// packed hi/lo bf16 split: hi = bf16x2(a,b) (a in low half), lo = residuals
__device__ __forceinline__ void split2(float a, float b, uint32_t& hi, uint32_t& lo) {
    asm("cvt.rn.bf16x2.f32 %0, %1, %2;" : "=r"(hi) : "f"(b), "f"(a));
    float ah = __uint_as_float(hi << 16);
    float bh = __uint_as_float(hi & 0xFFFF0000u);
    asm("cvt.rn.bf16x2.f32 %0, %1, %2;" : "=r"(lo) : "f"(b - bh), "f"(a - ah));
}

// 3-term emulated fp32 GEMM for this warp's 16x64 tile of a 64x128 output.
// wr in 0..3 (16-row strip), wc in 0..1 (64-col strip).
__device__ __forceinline__ void warp_gemm3(const char* sm, int wr, int wc,
                                           int lid, float acc[8][4]) {
    uint32_t sb = smem_u32(sm);
    uint32_t a_base = sb + A_HI + (uint32_t)(wr * 16 + (lid & 15)) * PITCH +
                      (uint32_t)((lid >> 4) * 8) * 2;
    uint32_t b_base = sb + B_HI +
        (uint32_t)(wc * 64 + ((lid >> 4) & 1) * 8 + (lid & 7)) * PITCH +
        (uint32_t)(((lid >> 3) & 1) * 8) * 2;
#pragma unroll
    for (int ks = 0; ks < 8; ks++) {
        uint32_t ko = ks * 32;
        uint32_t Ah[4], Al[4], Bh[4][4], Bl[4][4];
        ldsm4(a_base + ko, Ah);
        ldsm4(a_base + (A_LO - A_HI) + ko, Al);
#pragma unroll
        for (int g = 0; g < 4; g++) {
            ldsm4(b_base + g * 16 * PITCH + ko, Bh[g]);
            ldsm4(b_base + (B_LO - B_HI) + g * 16 * PITCH + ko, Bl[g]);
        }
#pragma unroll
        for (int g = 0; g < 4; g++)
#pragma unroll
            for (int s = 0; s < 2; s++) {
                float* c = acc[g * 2 + s];
                mma16816(c, Ah, &Bh[g][2 * s]);
                mma16816(c, Al, &Bh[g][2 * s]);
                mma16816(c, Ah, &Bl[g][2 * s]);
            }
    }
}

#define ZACC(acc)                                   \
    _Pragma("unroll") for (int _n = 0; _n < 8; _n++) \
    _Pragma("unroll") for (int _q = 0; _q < 4; _q++) acc[_n][_q] = 0.f;

// load a [64,128] f32 tile (row-clamped) -> bf16 hi/lo into A region
__device__ __forceinline__ void load_split_tile(const float* __restrict__ src,
                                                int base, int maxr, char* sm) {
    for (int g = threadIdx.x; g < 1024; g += 256) {
        int r = g >> 4, c8 = (g & 15) << 3;
        int rr = min(base + r, maxr - 1);
        const float* p = src + (size_t)rr * HH + c8;
        float4 v0 = *(const float4*)p;
        float4 v1 = *(const float4*)(p + 4);
        uint32_t h0, l0, h1, l1, h2, l2, h3, l3;
        split2(v0.x, v0.y, h0, l0); split2(v0.z, v0.w, h1, l1);
        split2(v1.x, v1.y, h2, l2); split2(v1.z, v1.w, h3, l3);
        char* dst = sm + (size_t)r * PITCH + c8 * 2;
        *(uint4*)(dst + A_HI) = make_uint4(h0, h1, h2, h3);
        *(uint4*)(dst + A_LO) = make_uint4(l0, l1, l2, l3);
    }
}

// copy packed weight matrix (hi 32KB + lo 32KB) into B region
__device__ __forceinline__ void copy_w(const __nv_bfloat16* __restrict__ w,
                                       char* sm) {
    const uint4* s = (const uint4*)w;
    for (int i = threadIdx.x; i < 2048; i += 256) {
        int r = i >> 4, c = i & 15;
        char* dst = sm + (size_t)r * PITCH + c * 16;
        *(uint4*)(dst + B_HI) = s[i];
        *(uint4*)(dst + B_LO) = s[i + 2048];
    }
}

// ============================ pack kernel ===================================
__global__ void pack_w(const float* __restrict__ src, int which, int stride) {
    __nv_bfloat16* dst =
        which == 0 ? g_wsrc : which == 1 ? g_wdst : which == 2 ? g_we :
        which == 3 ? g_we2  : which == 4 ? g_wnx  : which == 5 ? g_wna :
        which == 6 ? g_wn2  : which == 7 ? g_wne2 : g_wee2;
    int i = blockIdx.x * 256 + threadIdx.x;
    int m = i >> 14, t = i & 16383;
    int n = t >> 7, k = t & 127;
    float v = src[(size_t)m * stride + k * HH + n];   // transpose
    __nv_bfloat16 h = __float2bfloat16_rn(v);
    __nv_bfloat16 lo = __float2bfloat16_rn(v - __bfloat162float(h));
    __nv_bfloat16* b = dst + (size_t)m * 32768;
    b[t] = h;
    b[t + 16384] = lo;
}

// =========================== edge layer =====================================
__global__ __launch_bounds__(256, 2) void edge_layer_mma(
    int l, const float* __restrict__ b1, const float* __restrict__ b2,
    const int* __restrict__ rowi, const int* __restrict__ coli) {
    extern __shared__ __align__(16) char sm[];
    int tid = threadIdx.x, lid = tid & 31, wid = tid >> 5;
    int wr = wid >> 1, wc = wid & 1;
    int ebase = blockIdx.x * 64;
    int* rs = (int*)(sm + SM_IDX);
    int* cs = rs + 64;

    load_split_tile(g_e, ebase, EE, sm);
    copy_w(g_we + (size_t)l * 32768, sm);
    if (tid < 64) {
        int er = min(ebase + tid, EE - 1);
        rs[tid] = rowi[er];
        cs[tid] = coli[er];
    }
    __syncthreads();

    float acc[8][4];
    ZACC(acc);
    warp_gemm3(sm, wr, wc, lid, acc);
    __syncthreads();

    int lq = lid >> 2, lr = (lid & 3) * 2;
    int rA = wr * 16 + lq, rB = rA + 8;
    {
        const float* xsA = g_xs + (size_t)rs[rA] * HH;
        const float* xdA = g_xd + (size_t)cs[rA] * HH;
        const float* xsB = g_xs + (size_t)rs[rB] * HH;
        const float* xdB = g_xd + (size_t)cs[rB] * HH;
#pragma unroll
        for (int n = 0; n < 8; n++) {
            int col = wc * 64 + n * 8 + lr;
            float2 bv = *(const float2*)(b1 + col);
            float2 sA = *(const float2*)(xsA + col);
            float2 dA = *(const float2*)(xdA + col);
            float2 sB = *(const float2*)(xsB + col);
            float2 dB = *(const float2*)(xdB + col);
            float* c = acc[n];
            float h0 = fmaxf(c[0] + bv.x + sA.x + dA.x, 0.f);
            float h1 = fmaxf(c[1] + bv.y + sA.y + dA.y, 0.f);
            float h2 = fmaxf(c[2] + bv.x + sB.x + dB.x, 0.f);
            float h3 = fmaxf(c[3] + bv.y + sB.y + dB.y, 0.f);
            uint32_t hi, lo;
            split2(h0, h1, hi, lo);
            *(uint32_t*)(sm + A_HI + (size_t)rA * PITCH + col * 2) = hi;
            *(uint32_t*)(sm + A_LO + (size_t)rA * PITCH + col * 2) = lo;
            split2(h2, h3, hi, lo);
            *(uint32_t*)(sm + A_HI + (size_t)rB * PITCH + col * 2) = hi;
            *(uint32_t*)(sm + A_LO + (size_t)rB * PITCH + col * 2) = lo;
        }
    }
    copy_w(g_we2 + (size_t)l * 32768, sm);
    __syncthreads();

    ZACC(acc);
    warp_gemm3(sm, wr, wc, lid, acc);

    int eA = ebase + rA, eB = ebase + rB;
    float* aggA = g_agg + (size_t)rs[rA] * HH;
    float* aggB = g_agg + (size_t)rs[rB] * HH;
#pragma unroll
    for (int n = 0; n < 8; n++) {
        int col = wc * 64 + n * 8 + lr;
        float2 bv = *(const float2*)(b2 + col);
        float* c = acc[n];
        if (eA < EE) {
            float vx = c[0] + bv.x, vy = c[1] + bv.y;
            *(float2*)(g_e + (size_t)eA * HH + col) = make_float2(vx, vy);
            asm volatile("red.global.add.v2.f32 [%0], {%1, %2};"
                         :: "l"(aggA + col), "f"(vx), "f"(vy) : "memory");
        }
        if (eB < EE) {
            float vx = c[2] + bv.x, vy = c[3] + bv.y;
            *(float2*)(g_e + (size_t)eB * HH + col) = make_float2(vx, vy);
            asm volatile("red.global.add.v2.f32 [%0], {%1, %2};"
                         :: "l"(aggB + col), "f"(vx), "f"(vy) : "memory");
        }
    }
}

// ======== xs/xd projections (+ zero g_agg slice for the coming edge pass) ===
__global__ __launch_bounds__(256, 2) void xsxd_mma(int l) {
    extern __shared__ __align__(16) char sm[];
    int tid = threadIdx.x, lid = tid & 31, wid = tid >> 5;
    int wr = wid >> 1, wc = wid & 1;
    int base = blockIdx.x * 64;

    // zero this CTA's agg slice
    for (int i = tid; i < 2048; i += 256) {
        int r = i >> 5, c4 = i & 31;
        if (base + r < NN)
            ((float4*)g_agg)[(size_t)(base + r) * 32 + c4] =
                make_float4(0.f, 0.f, 0.f, 0.f);
    }

    load_split_tile(g_x, base, NN, sm);
    copy_w(g_wsrc + (size_t)l * 32768, sm);
    __syncthreads();

    float acc[8][4];
    ZACC(acc);
    warp_gemm3(sm, wr, wc, lid, acc);

    int lq = lid >> 2, lr = (lid & 3) * 2;
    int rA = wr * 16 + lq, rB = rA + 8;
#pragma unroll
    for (int n = 0; n < 8; n++) {
        int col = wc * 64 + n * 8 + lr;
        float* c = acc[n];
        if (base + rA < NN)
            *(float2*)(g_xs + (size_t)(base + rA) * HH + col) =
                make_float2(c[0], c[1]);
        if (base + rB < NN)
            *(float2*)(g_xs + (size_t)(base + rB) * HH + col) =
                make_float2(c[2], c[3]);
    }
    __syncthreads();
    copy_w(g_wdst + (size_t)l * 32768, sm);
    __syncthreads();

    ZACC(acc);
    warp_gemm3(sm, wr, wc, lid, acc);
#pragma unroll
    for (int n = 0; n < 8; n++) {
        int col = wc * 64 + n * 8 + lr;
        float* c = acc[n];
        if (base + rA < NN)
            *(float2*)(g_xd + (size_t)(base + rA) * HH + col) =
                make_float2(c[0], c[1]);
        if (base + rB < NN)
            *(float2*)(g_xd + (size_t)(base + rB) * HH + col) =
                make_float2(c[2], c[3]);
    }
}

// =========================== node layer =====================================
__global__ __launch_bounds__(256, 2) void node_layer_mma(
    int l, const float* __restrict__ b1, const float* __restrict__ b2) {
    extern __shared__ __align__(16) char sm[];
    int tid = threadIdx.x, lid = tid & 31, wid = tid >> 5;
    int wr = wid >> 1, wc = wid & 1;
    int base = blockIdx.x * 64;

    load_split_tile(g_x, base, NN, sm);
    copy_w(g_wnx + (size_t)l * 32768, sm);
    __syncthreads();

    float acc[8][4];
    ZACC(acc);
    warp_gemm3(sm, wr, wc, lid, acc);
    __syncthreads();

    load_split_tile(g_agg, base, NN, sm);
    copy_w(g_wna + (size_t)l * 32768, sm);
    __syncthreads();
    warp_gemm3(sm, wr, wc, lid, acc);   // accumulate second term
    __syncthreads();

    int lq = lid >> 2, lr = (lid & 3) * 2;
    int rA = wr * 16 + lq, rB = rA + 8;
#pragma unroll
    for (int n = 0; n < 8; n++) {
        int col = wc * 64 + n * 8 + lr;
        float2 bv = *(const float2*)(b1 + col);
        float* c = acc[n];
        float h0 = fmaxf(c[0] + bv.x, 0.f);
        float h1 = fmaxf(c[1] + bv.y, 0.f);
        float h2 = fmaxf(c[2] + bv.x, 0.f);
        float h3 = fmaxf(c[3] + bv.y, 0.f);
        uint32_t hi, lo;
        split2(h0, h1, hi, lo);
        *(uint32_t*)(sm + A_HI + (size_t)rA * PITCH + col * 2) = hi;
        *(uint32_t*)(sm + A_LO + (size_t)rA * PITCH + col * 2) = lo;
        split2(h2, h3, hi, lo);
        *(uint32_t*)(sm + A_HI + (size_t)rB * PITCH + col * 2) = hi;
        *(uint32_t*)(sm + A_LO + (size_t)rB * PITCH + col * 2) = lo;
    }
    copy_w(g_wn2 + (size_t)l * 32768, sm);
    __syncthreads();

    ZACC(acc);
    warp_gemm3(sm, wr, wc, lid, acc);

#pragma unroll
    for (int n = 0; n < 8; n++) {
        int col = wc * 64 + n * 8 + lr;
        float2 bv = *(const float2*)(b2 + col);
        float* c = acc[n];
        if (base + rA < NN) {
            float* xp = g_x + (size_t)(base + rA) * HH + col;
            float2 xv = *(float2*)xp;
            *(float2*)xp = make_float2(c[0] + bv.x + xv.x, c[1] + bv.y + xv.y);
        }
        if (base + rB < NN) {
            float* xp = g_x + (size_t)(base + rB) * HH + col;
            float2 xv = *(float2*)xp;
            *(float2*)xp = make_float2(c[2] + bv.x + xv.x, c[3] + bv.y + xv.y);
        }
    }
}

// ============================ encoders ======================================
template <int K1, int DST>
__global__ __launch_bounds__(256, 2) void encoder_mma(
    const float* __restrict__ in, const float* __restrict__ w1,
    const float* __restrict__ b1, const float* __restrict__ b2, int rows) {
    extern __shared__ __align__(16) char sm[];
    int tid = threadIdx.x, lid = tid & 31, wid = tid >> 5;
    int wr = wid >> 1, wc = wid & 1;
    int base = blockIdx.x * 64;

    for (int g = tid; g < 1024; g += 256) {
        int r = g >> 4, c8 = (g & 15) << 3;
        int rr = min(base + r, rows - 1);
        float vin[K1];
#pragma unroll
        for (int k = 0; k < K1; k++) vin[k] = in[(size_t)rr * K1 + k];
        float h[8];
#pragma unroll
        for (int c = 0; c < 8; c++) {
            int cc = c8 + c;
            float s = b1[cc];
#pragma unroll
            for (int k = 0; k < K1; k++) s += vin[k] * w1[k * HH + cc];
            h[c] = fmaxf(s, 0.f);
        }
        uint32_t hv[4], lv[4];
        split2(h[0], h[1], hv[0], lv[0]);
        split2(h[2], h[3], hv[1], lv[1]);
        split2(h[4], h[5], hv[2], lv[2]);
        split2(h[6], h[7], hv[3], lv[3]);
        char* dst = sm + (size_t)r * PITCH + c8 * 2;
        *(uint4*)(dst + A_HI) = make_uint4(hv[0], hv[1], hv[2], hv[3]);
        *(uint4*)(dst + A_LO) = make_uint4(lv[0], lv[1], lv[2], lv[3]);
    }
    copy_w(DST ? g_wee2 : g_wne2, sm);
    __syncthreads();

    float acc[8][4];
    ZACC(acc);
    warp_gemm3(sm, wr, wc, lid, acc);

    float* out = DST ? g_e : g_x;
    int lq = lid >> 2, lr = (lid & 3) * 2;
    int rA = wr * 16 + lq, rB = rA + 8;
#pragma unroll
    for (int n = 0; n < 8; n++) {
        int col = wc * 64 + n * 8 + lr;
        float2 bv = *(const float2*)(b2 + col);
        float* c = acc[n];
        if (base + rA < rows)
            *(float2*)(out + (size_t)(base + rA) * HH + col) =
                make_float2(c[0] + bv.x, c[1] + bv.y);
        if (base + rB < rows)
            *(float2*)(out + (size_t)(base + rB) * HH + col) =
                make_float2(c[2] + bv.x, c[3] + bv.y);
    }
}

// ============================ decoder (scalar) ==============================
__global__ __launch_bounds__(256) void decoder_kernel(
    const float* __restrict__ w1, const float* __restrict__ b1,
    const float* __restrict__ w2, const float* __restrict__ b2,
    float* __restrict__ out) {
    __shared__ __align__(16) float As[64 * HH];
    int tid = threadIdx.x;
    int base = blockIdx.x * 64;
    int lane = tid & 31, wrow = tid >> 5;
    int j0 = lane * 4, r0 = wrow * 8;

    for (int i = tid; i < 64 * 32; i += 256) {
        int r = i >> 5, c4 = i & 31;
        int nr = min(base + r, NN - 1);
        ((float4*)As)[r * 32 + c4] = ((const float4*)g_x)[(size_t)nr * 32 + c4];
    }
    __syncthreads();

    float acc[8][4];
    float4 bb = *(const float4*)(b1 + j0);
#pragma unroll
    for (int r = 0; r < 8; r++) {
        acc[r][0] = bb.x; acc[r][1] = bb.y; acc[r][2] = bb.z; acc[r][3] = bb.w;
    }
#pragma unroll 2
    for (int k4 = 0; k4 < 32; k4++) {
        const float* wr = w1 + (k4 * 4) * HH + j0;
        float4 w0 = *(const float4*)(wr);
        float4 w1v = *(const float4*)(wr + HH);
        float4 w2v = *(const float4*)(wr + 2 * HH);
        float4 w3v = *(const float4*)(wr + 3 * HH);
#pragma unroll
        for (int r = 0; r < 8; r++) {
            float4 a = *(const float4*)(As + (r0 + r) * HH + k4 * 4);
            acc[r][0] += a.x * w0.x + a.y * w1v.x + a.z * w2v.x + a.w * w3v.x;
            acc[r][1] += a.x * w0.y + a.y * w1v.y + a.z * w2v.y + a.w * w3v.y;
            acc[r][2] += a.x * w0.z + a.y * w1v.z + a.z * w2v.z + a.w * w3v.z;
            acc[r][3] += a.x * w0.w + a.y * w1v.w + a.z * w2v.w + a.w * w3v.w;
        }
    }
    __syncthreads();
#pragma unroll
    for (int r = 0; r < 8; r++) {
        float4 h = make_float4(fmaxf(acc[r][0], 0.f), fmaxf(acc[r][1], 0.f),
                               fmaxf(acc[r][2], 0.f), fmaxf(acc[r][3], 0.f));
        *(float4*)(As + (r0 + r) * HH + j0) = h;
    }
    __syncthreads();

    if (tid < 192) {
        int r = tid / 3, c = tid - r * 3;
        float s = b2[c];
#pragma unroll 4
        for (int k = 0; k < HH; k++) s += As[r * HH + k] * w2[k * 3 + c];
        int nr = base + r;
        if (nr < NN) out[nr * 3 + c] = s;
    }
}

// ============================================================================
extern "C" void kernel_launch(void* const* d_in, const int* in_sizes, int n_in,
                              void* d_out, int out_size) {
    const float* x_in    = (const float*)d_in[0];
    const float* eattr   = (const float*)d_in[1];
    const float* ne_w1   = (const float*)d_in[2];
    const float* ne_b1   = (const float*)d_in[3];
    const float* ne_w2   = (const float*)d_in[4];
    const float* ne_b2   = (const float*)d_in[5];
    const float* ee_w1   = (const float*)d_in[6];
    const float* ee_b1   = (const float*)d_in[7];
    const float* ee_w2   = (const float*)d_in[8];
    const float* ee_b2   = (const float*)d_in[9];
    const float* edge_w1 = (const float*)d_in[10];
    const float* edge_b1 = (const float*)d_in[11];
    const float* edge_w2 = (const float*)d_in[12];
    const float* edge_b2 = (const float*)d_in[13];
    const float* node_w1 = (const float*)d_in[14];
    const float* node_b1 = (const float*)d_in[15];
    const float* node_w2 = (const float*)d_in[16];
    const float* node_b2 = (const float*)d_in[17];
    const float* nd_w1   = (const float*)d_in[18];
    const float* nd_b1   = (const float*)d_in[19];
    const float* nd_w2   = (const float*)d_in[20];
    const float* nd_b2   = (const float*)d_in[21];
    const int*   eidx    = (const int*)d_in[22];
    const int*   rowi    = eidx;
    const int*   coli    = eidx + EE;

    cudaFuncSetAttribute(edge_layer_mma,
                         cudaFuncAttributeMaxDynamicSharedMemorySize, SMEM_SZ);
    cudaFuncSetAttribute(xsxd_mma,
                         cudaFuncAttributeMaxDynamicSharedMemorySize, SMEM_SZ);
    cudaFuncSetAttribute(node_layer_mma,
                         cudaFuncAttributeMaxDynamicSharedMemorySize, SMEM_SZ);
    cudaFuncSetAttribute(encoder_mma<6, 0>,
                         cudaFuncAttributeMaxDynamicSharedMemorySize, SMEM_SZ);
    cudaFuncSetAttribute(encoder_mma<3, 1>,
                         cudaFuncAttributeMaxDynamicSharedMemorySize, SMEM_SZ);

    // pack weights: transpose + bf16 hi/lo split
    pack_w<<<LL * 64, 256>>>(edge_w1,             0, 3 * 16384);
    pack_w<<<LL * 64, 256>>>(edge_w1 + 16384,     1, 3 * 16384);
    pack_w<<<LL * 64, 256>>>(edge_w1 + 2 * 16384, 2, 3 * 16384);
    pack_w<<<LL * 64, 256>>>(edge_w2,             3, 16384);
    pack_w<<<LL * 64, 256>>>(node_w1,             4, 2 * 16384);
    pack_w<<<LL * 64, 256>>>(node_w1 + 16384,     5, 2 * 16384);
    pack_w<<<LL * 64, 256>>>(node_w2,             6, 16384);
    pack_w<<<64, 256>>>(ne_w2, 7, 16384);
    pack_w<<<64, 256>>>(ee_w2, 8, 16384);

    const int TB_N = (NN + 63) / 64;   // 313
    const int TB_E = (EE + 63) / 64;   // 4688

    encoder_mma<6, 0><<<TB_N, 256, SMEM_SZ>>>(x_in, ne_w1, ne_b1, ne_b2, NN);
    encoder_mma<3, 1><<<TB_E, 256, SMEM_SZ>>>(eattr, ee_w1, ee_b1, ee_b2, EE);

    for (int l = 0; l < LL; l++) {
        xsxd_mma<<<TB_N, 256, SMEM_SZ>>>(l);
        edge_layer_mma<<<TB_E, 256, SMEM_SZ>>>(l, edge_b1 + l * HH,
                                               edge_b2 + l * HH, rowi, coli);
        node_layer_mma<<<TB_N, 256, SMEM_SZ>>>(l, node_b1 + l * HH,
                                               node_b2 + l * HH);
    }

    decoder_kernel<<<TB_N, 256>>>(nd_w1, nd_b1, nd_w2, nd_b2, (float*)d_out);
}

// round 6
// speedup vs baseline: 1.3177x; 1.3177x over previous
#include <cuda_runtime.h>
#include <cuda_bf16.h>
#include <cstdint>

#define NN 20000
#define EE 300000
#define HH 128
#define LL 8
#define PITCH 272   // smem row pitch bytes (136 bf16) — conflict-free ldmatrix
#define NSM 148

// 128-row-tile smem layout (bytes)
#define A_HI 0
#define A_LO 34816
#define B_HI 69632          // generic kernels: single weight (hi/lo) region
#define B_LO 104448
#define G_IDX 139264
#define G_SMEM 140288
// persistent edge kernel: two resident weights
#define W1_HI 69632
#define W2_HI 139264
#define E_IDX 208896
#define E_SMEM 209920

// ============================ scratch globals ===============================
__device__ __align__(16) float g_x  [NN * HH];
__device__ __align__(16) float g_e  [EE * HH];
__device__ __align__(16) float g_xs [NN * HH];
__device__ __align__(16) float g_xd [NN * HH];
__device__ __align__(16) float g_agg[NN * HH];

// packed weights: per matrix [hi 128x128 | lo 128x128] bf16, TRANSPOSED
__device__ __align__(16) __nv_bfloat16 g_wsrc[LL * 32768];
__device__ __align__(16) __nv_bfloat16 g_wdst[LL * 32768];
__device__ __align__(16) __nv_bfloat16 g_we  [LL * 32768];
__device__ __align__(16) __nv_bfloat16 g_we2 [LL * 32768];
__device__ __align__(16) __nv_bfloat16 g_wnx [LL * 32768];
__device__ __align__(16) __nv_bfloat16 g_wna [LL * 32768];
__device__ __align__(16) __nv_bfloat16 g_wn2 [LL * 32768];
__device__ __align__(16) __nv_bfloat16 g_wne2[32768];
__device__ __align__(16) __nv_bfloat16 g_wee2[32768];

// ============================ helpers =======================================
__device__ __forceinline__ uint32_t smem_u32(const void* p) {
    uint32_t a;
    asm("{ .reg .u64 t; cvta.to.shared.u64 t, %1; cvt.u32.u64 %0, t; }"
        : "=r"(a) : "l"(p));
    return a;
}
__device__ __forceinline__ void ldsm4(uint32_t addr, uint32_t r[4]) {
    asm volatile("ldmatrix.sync.aligned.m8n8.x4.shared.b16 {%0,%1,%2,%3}, [%4];"
                 : "=r"(r[0]), "=r"(r[1]), "=r"(r[2]), "=r"(r[3]) : "r"(addr));
}
__device__ __forceinline__ void mma16816(float c[4], const uint32_t a[4],
                                         const uint32_t* b) {
    asm volatile("mma.sync.aligned.m16n8k16.row.col.f32.bf16.bf16.f32 "
                 "{%0,%1,%2,%3}, {%4,%5,%6,%7}, {%8,%9}, {%0,%1,%2,%3};"
                 : "+f"(c[0]), "+f"(c[1]), "+f"(c[2]), "+f"(c[3])
                 : "r"(a[0]), "r"(a[1]), "r"(a[2]), "r"(a[3]),
                   "r"(b[0]), "r"(b[1]));
}

// packed hi/lo bf16 split
__device__ __forceinline__ void split2(float a, float b, uint32_t& hi, uint32_t& lo) {
    asm("cvt.rn.bf16x2.f32 %0, %1, %2;" : "=r"(hi) : "f"(b), "f"(a));
    float ah = __uint_as_float(hi << 16);
    float bh = __uint_as_float(hi & 0xFFFF0000u);
    asm("cvt.rn.bf16x2.f32 %0, %1, %2;" : "=r"(lo) : "f"(b - bh), "f"(a - ah));
}

// 3-term emulated fp32 GEMM, warp tile 32x64 of a 128x128 output.
// b_off: smem byte offset of the weight hi region (lo at +34816).
__device__ __forceinline__ void warp_gemm3(const char* sm, uint32_t b_off,
                                           int wr, int wc, int lid,
                                           float acc[2][8][4]) {
    uint32_t sb = smem_u32(sm);
    uint32_t a_base = sb + A_HI + (uint32_t)(wr * 32 + (lid & 15)) * PITCH +
                      (uint32_t)((lid >> 4) * 8) * 2;
    uint32_t b_base = sb + b_off +
        (uint32_t)(wc * 64 + ((lid >> 4) & 1) * 8 + (lid & 7)) * PITCH +
        (uint32_t)(((lid >> 3) & 1) * 8) * 2;
#pragma unroll
    for (int ks = 0; ks < 8; ks++) {
        uint32_t ko = ks * 32;
        uint32_t Ah[2][4], Al[2][4], Bh[4][4], Bl[4][4];
        ldsm4(a_base + ko, Ah[0]);
        ldsm4(a_base + 16 * PITCH + ko, Ah[1]);
        ldsm4(a_base + 34816 + ko, Al[0]);
        ldsm4(a_base + 34816 + 16 * PITCH + ko, Al[1]);
#pragma unroll
        for (int g = 0; g < 4; g++) {
            ldsm4(b_base + g * 16 * PITCH + ko, Bh[g]);
            ldsm4(b_base + 34816 + g * 16 * PITCH + ko, Bl[g]);
        }
#pragma unroll
        for (int m = 0; m < 2; m++)
#pragma unroll
            for (int g = 0; g < 4; g++)
#pragma unroll
                for (int s = 0; s < 2; s++) {
                    float* c = acc[m][g * 2 + s];
                    mma16816(c, Ah[m], &Bh[g][2 * s]);
                    mma16816(c, Al[m], &Bh[g][2 * s]);
                    mma16816(c, Ah[m], &Bl[g][2 * s]);
                }
    }
}

#define ZACC(acc)                                   \
    _Pragma("unroll") for (int _m = 0; _m < 2; _m++) \
    _Pragma("unroll") for (int _n = 0; _n < 8; _n++) \
    _Pragma("unroll") for (int _q = 0; _q < 4; _q++) acc[_m][_n][_q] = 0.f;

// load [128,128] f32 tile (row-clamped) -> bf16 hi/lo into A region
__device__ __forceinline__ void load_split_tile(const float* __restrict__ src,
                                                int base, int maxr, char* sm) {
    for (int g = threadIdx.x; g < 2048; g += 256) {
        int r = g >> 4, c8 = (g & 15) << 3;
        int rr = min(base + r, maxr - 1);
        const float* p = src + (size_t)rr * HH + c8;
        float4 v0 = *(const float4*)p;
        float4 v1 = *(const float4*)(p + 4);
        uint32_t h0, l0, h1, l1, h2, l2, h3, l3;
        split2(v0.x, v0.y, h0, l0); split2(v0.z, v0.w, h1, l1);
        split2(v1.x, v1.y, h2, l2); split2(v1.z, v1.w, h3, l3);
        char* dst = sm + (size_t)r * PITCH + c8 * 2;
        *(uint4*)(dst + A_HI) = make_uint4(h0, h1, h2, h3);
        *(uint4*)(dst + A_LO) = make_uint4(l0, l1, l2, l3);
    }
}

// copy packed weight matrix (hi 32KB + lo 32KB) into smem at off_hi
__device__ __forceinline__ void copy_w(const __nv_bfloat16* __restrict__ w,
                                       char* sm, uint32_t off_hi) {
    const uint4* s = (const uint4*)w;
    for (int i = threadIdx.x; i < 2048; i += 256) {
        int r = i >> 4, c = i & 15;
        char* dst = sm + off_hi + (size_t)r * PITCH + c * 16;
        *(uint4*)(dst) = s[i];
        *(uint4*)(dst + 34816) = s[i + 2048];
    }
}

// ============================ pack kernel ===================================
__global__ void pack_w(const float* __restrict__ src, int which, int stride) {
    __nv_bfloat16* dst =
        which == 0 ? g_wsrc : which == 1 ? g_wdst : which == 2 ? g_we :
        which == 3 ? g_we2  : which == 4 ? g_wnx  : which == 5 ? g_wna :
        which == 6 ? g_wn2  : which == 7 ? g_wne2 : g_wee2;
    int i = blockIdx.x * 256 + threadIdx.x;
    int m = i >> 14, t = i & 16383;
    int n = t >> 7, k = t & 127;
    float v = src[(size_t)m * stride + k * HH + n];   // transpose
    __nv_bfloat16 h = __float2bfloat16_rn(v);
    __nv_bfloat16 lo = __float2bfloat16_rn(v - __bfloat162float(h));
    __nv_bfloat16* b = dst + (size_t)m * 32768;
    b[t] = h;
    b[t + 16384] = lo;
}

// ================= persistent edge layer (weights resident) =================
__global__ __launch_bounds__(256, 1) void edge_layer_persist(
    int l, const float* __restrict__ b1, const float* __restrict__ b2,
    const int* __restrict__ rowi, const int* __restrict__ coli, int ntiles) {
    extern __shared__ __align__(16) char sm[];
    int tid = threadIdx.x, lid = tid & 31, wid = tid >> 5;
    int wr = wid >> 1, wc = wid & 1;
    int* rs = (int*)(sm + E_IDX);
    int* cs = rs + 128;

    copy_w(g_we + (size_t)l * 32768, sm, W1_HI);
    copy_w(g_we2 + (size_t)l * 32768, sm, W2_HI);

    int lq = lid >> 2, lr = (lid & 3) * 2;

    for (int t = blockIdx.x; t < ntiles; t += gridDim.x) {
        int ebase = t * 128;
        __syncthreads();   // previous iter's smem reads done; weights ready
        load_split_tile(g_e, ebase, EE, sm);
        if (tid < 128) {
            int er = min(ebase + tid, EE - 1);
            rs[tid] = rowi[er];
            cs[tid] = coli[er];
        }
        __syncthreads();

        float acc[2][8][4];
        ZACC(acc);
        warp_gemm3(sm, W1_HI, wr, wc, lid, acc);
        __syncthreads();

#pragma unroll
        for (int m = 0; m < 2; m++) {
            int rA = wr * 32 + m * 16 + lq, rB = rA + 8;
            const float* xsA = g_xs + (size_t)rs[rA] * HH;
            const float* xdA = g_xd + (size_t)cs[rA] * HH;
            const float* xsB = g_xs + (size_t)rs[rB] * HH;
            const float* xdB = g_xd + (size_t)cs[rB] * HH;
#pragma unroll
            for (int n = 0; n < 8; n++) {
                int col = wc * 64 + n * 8 + lr;
                float2 bv = *(const float2*)(b1 + col);
                float2 sA = *(const float2*)(xsA + col);
                float2 dA = *(const float2*)(xdA + col);
                float2 sB = *(const float2*)(xsB + col);
                float2 dB = *(const float2*)(xdB + col);
                float* c = acc[m][n];
                float h0 = fmaxf(c[0] + bv.x + sA.x + dA.x, 0.f);
                float h1 = fmaxf(c[1] + bv.y + sA.y + dA.y, 0.f);
                float h2 = fmaxf(c[2] + bv.x + sB.x + dB.x, 0.f);
                float h3 = fmaxf(c[3] + bv.y + sB.y + dB.y, 0.f);
                uint32_t hi, lo;
                split2(h0, h1, hi, lo);
                *(uint32_t*)(sm + A_HI + (size_t)rA * PITCH + col * 2) = hi;
                *(uint32_t*)(sm + A_LO + (size_t)rA * PITCH + col * 2) = lo;
                split2(h2, h3, hi, lo);
                *(uint32_t*)(sm + A_HI + (size_t)rB * PITCH + col * 2) = hi;
                *(uint32_t*)(sm + A_LO + (size_t)rB * PITCH + col * 2) = lo;
            }
        }
        __syncthreads();

        ZACC(acc);
        warp_gemm3(sm, W2_HI, wr, wc, lid, acc);

#pragma unroll
        for (int m = 0; m < 2; m++) {
            int rA = wr * 32 + m * 16 + lq, rB = rA + 8;
            int eA = ebase + rA, eB = ebase + rB;
            float* aggA = g_agg + (size_t)rs[rA] * HH;
            float* aggB = g_agg + (size_t)rs[rB] * HH;
#pragma unroll
            for (int n = 0; n < 8; n++) {
                int col = wc * 64 + n * 8 + lr;
                float2 bv = *(const float2*)(b2 + col);
                float* c = acc[m][n];
                if (eA < EE) {
                    float vx = c[0] + bv.x, vy = c[1] + bv.y;
                    *(float2*)(g_e + (size_t)eA * HH + col) = make_float2(vx, vy);
                    asm volatile("red.global.add.v2.f32 [%0], {%1, %2};"
                                 :: "l"(aggA + col), "f"(vx), "f"(vy) : "memory");
                }
                if (eB < EE) {
                    float vx = c[2] + bv.x, vy = c[3] + bv.y;
                    *(float2*)(g_e + (size_t)eB * HH + col) = make_float2(vx, vy);
                    asm volatile("red.global.add.v2.f32 [%0], {%1, %2};"
                                 :: "l"(aggB + col), "f"(vx), "f"(vy) : "memory");
                }
            }
        }
    }
}

// ======== xs/xd projections (+ zero g_agg slice for the coming edge pass) ===
__global__ __launch_bounds__(256, 1) void xsxd_mma(int l) {
    extern __shared__ __align__(16) char sm[];
    int tid = threadIdx.x, lid = tid & 31, wid = tid >> 5;
    int wr = wid >> 1, wc = wid & 1;
    int base = blockIdx.x * 128;

    for (int i = tid; i < 4096; i += 256) {
        int r = i >> 5, c4 = i & 31;
        if (base + r < NN)
            ((float4*)g_agg)[(size_t)(base + r) * 32 + c4] =
                make_float4(0.f, 0.f, 0.f, 0.f);
    }

    load_split_tile(g_x, base, NN, sm);
    copy_w(g_wsrc + (size_t)l * 32768, sm, B_HI);
    __syncthreads();

    float acc[2][8][4];
    ZACC(acc);
    warp_gemm3(sm, B_HI, wr, wc, lid, acc);

    int lq = lid >> 2, lr = (lid & 3) * 2;
#pragma unroll
    for (int m = 0; m < 2; m++) {
        int rA = wr * 32 + m * 16 + lq, rB = rA + 8;
#pragma unroll
        for (int n = 0; n < 8; n++) {
            int col = wc * 64 + n * 8 + lr;
            float* c = acc[m][n];
            if (base + rA < NN)
                *(float2*)(g_xs + (size_t)(base + rA) * HH + col) =
                    make_float2(c[0], c[1]);
            if (base + rB < NN)
                *(float2*)(g_xs + (size_t)(base + rB) * HH + col) =
                    make_float2(c[2], c[3]);
        }
    }
    __syncthreads();
    copy_w(g_wdst + (size_t)l * 32768, sm, B_HI);
    __syncthreads();

    ZACC(acc);
    warp_gemm3(sm, B_HI, wr, wc, lid, acc);
#pragma unroll
    for (int m = 0; m < 2; m++) {
        int rA = wr * 32 + m * 16 + lq, rB = rA + 8;
#pragma unroll
        for (int n = 0; n < 8; n++) {
            int col = wc * 64 + n * 8 + lr;
            float* c = acc[m][n];
            if (base + rA < NN)
                *(float2*)(g_xd + (size_t)(base + rA) * HH + col) =
                    make_float2(c[0], c[1]);
            if (base + rB < NN)
                *(float2*)(g_xd + (size_t)(base + rB) * HH + col) =
                    make_float2(c[2], c[3]);
        }
    }
}

// =========================== node layer =====================================
__global__ __launch_bounds__(256, 1) void node_layer_mma(
    int l, const float* __restrict__ b1, const float* __restrict__ b2) {
    extern __shared__ __align__(16) char sm[];
    int tid = threadIdx.x, lid = tid & 31, wid = tid >> 5;
    int wr = wid >> 1, wc = wid & 1;
    int base = blockIdx.x * 128;

    load_split_tile(g_x, base, NN, sm);
    copy_w(g_wnx + (size_t)l * 32768, sm, B_HI);
    __syncthreads();

    float acc[2][8][4];
    ZACC(acc);
    warp_gemm3(sm, B_HI, wr, wc, lid, acc);
    __syncthreads();

    load_split_tile(g_agg, base, NN, sm);
    copy_w(g_wna + (size_t)l * 32768, sm, B_HI);
    __syncthreads();
    warp_gemm3(sm, B_HI, wr, wc, lid, acc);
    __syncthreads();

    int lq = lid >> 2, lr = (lid & 3) * 2;
#pragma unroll
    for (int m = 0; m < 2; m++) {
        int rA = wr * 32 + m * 16 + lq, rB = rA + 8;
#pragma unroll
        for (int n = 0; n < 8; n++) {
            int col = wc * 64 + n * 8 + lr;
            float2 bv = *(const float2*)(b1 + col);
            float* c = acc[m][n];
            float h0 = fmaxf(c[0] + bv.x, 0.f);
            float h1 = fmaxf(c[1] + bv.y, 0.f);
            float h2 = fmaxf(c[2] + bv.x, 0.f);
            float h3 = fmaxf(c[3] + bv.y, 0.f);
            uint32_t hi, lo;
            split2(h0, h1, hi, lo);
            *(uint32_t*)(sm + A_HI + (size_t)rA * PITCH + col * 2) = hi;
            *(uint32_t*)(sm + A_LO + (size_t)rA * PITCH + col * 2) = lo;
            split2(h2, h3, hi, lo);
            *(uint32_t*)(sm + A_HI + (size_t)rB * PITCH + col * 2) = hi;
            *(uint32_t*)(sm + A_LO + (size_t)rB * PITCH + col * 2) = lo;
        }
    }
    copy_w(g_wn2 + (size_t)l * 32768, sm, B_HI);
    __syncthreads();

    ZACC(acc);
    warp_gemm3(sm, B_HI, wr, wc, lid, acc);

#pragma unroll
    for (int m = 0; m < 2; m++) {
        int rA = wr * 32 + m * 16 + lq, rB = rA + 8;
#pragma unroll
        for (int n = 0; n < 8; n++) {
            int col = wc * 64 + n * 8 + lr;
            float2 bv = *(const float2*)(b2 + col);
            float* c = acc[m][n];
            if (base + rA < NN) {
                float* xp = g_x + (size_t)(base + rA) * HH + col;
                float2 xv = *(float2*)xp;
                *(float2*)xp = make_float2(c[0] + bv.x + xv.x, c[1] + bv.y + xv.y);
            }
            if (base + rB < NN) {
                float* xp = g_x + (size_t)(base + rB) * HH + col;
                float2 xv = *(float2*)xp;
                *(float2*)xp = make_float2(c[2] + bv.x + xv.x, c[3] + bv.y + xv.y);
            }
        }
    }
}

// ==================== encoders (persistent, W resident) =====================
template <int K1, int DST>
__global__ __launch_bounds__(256, 1) void encoder_mma(
    const float* __restrict__ in, const float* __restrict__ w1,
    const float* __restrict__ b1, const float* __restrict__ b2,
    int rows, int ntiles) {
    extern __shared__ __align__(16) char sm[];
    int tid = threadIdx.x, lid = tid & 31, wid = tid >> 5;
    int wr = wid >> 1, wc = wid & 1;

    copy_w(DST ? g_wee2 : g_wne2, sm, B_HI);
    int lq = lid >> 2, lr = (lid & 3) * 2;

    for (int t = blockIdx.x; t < ntiles; t += gridDim.x) {
        int base = t * 128;
        __syncthreads();
        for (int g = tid; g < 2048; g += 256) {
            int r = g >> 4, c8 = (g & 15) << 3;
            int rr = min(base + r, rows - 1);
            float vin[K1];
#pragma unroll
            for (int k = 0; k < K1; k++) vin[k] = in[(size_t)rr * K1 + k];
            float h[8];
#pragma unroll
            for (int c = 0; c < 8; c++) {
                int cc = c8 + c;
                float s = b1[cc];
#pragma unroll
                for (int k = 0; k < K1; k++) s += vin[k] * w1[k * HH + cc];
                h[c] = fmaxf(s, 0.f);
            }
            uint32_t hv[4], lv[4];
            split2(h[0], h[1], hv[0], lv[0]);
            split2(h[2], h[3], hv[1], lv[1]);
            split2(h[4], h[5], hv[2], lv[2]);
            split2(h[6], h[7], hv[3], lv[3]);
            char* dst = sm + (size_t)r * PITCH + c8 * 2;
            *(uint4*)(dst + A_HI) = make_uint4(hv[0], hv[1], hv[2], hv[3]);
            *(uint4*)(dst + A_LO) = make_uint4(lv[0], lv[1], lv[2], lv[3]);
        }
        __syncthreads();

        float acc[2][8][4];
        ZACC(acc);
        warp_gemm3(sm, B_HI, wr, wc, lid, acc);

        float* out = DST ? g_e : g_x;
#pragma unroll
        for (int m = 0; m < 2; m++) {
            int rA = wr * 32 + m * 16 + lq, rB = rA + 8;
#pragma unroll
            for (int n = 0; n < 8; n++) {
                int col = wc * 64 + n * 8 + lr;
                float2 bv = *(const float2*)(b2 + col);
                float* c = acc[m][n];
                if (base + rA < rows)
                    *(float2*)(out + (size_t)(base + rA) * HH + col) =
                        make_float2(c[0] + bv.x, c[1] + bv.y);
                if (base + rB < rows)
                    *(float2*)(out + (size_t)(base + rB) * HH + col) =
                        make_float2(c[2] + bv.x, c[3] + bv.y);
            }
        }
    }
}

// ============================ decoder (scalar) ==============================
__global__ __launch_bounds__(256) void decoder_kernel(
    const float* __restrict__ w1, const float* __restrict__ b1,
    const float* __restrict__ w2, const float* __restrict__ b2,
    float* __restrict__ out) {
    __shared__ __align__(16) float As[64 * HH];
    int tid = threadIdx.x;
    int base = blockIdx.x * 64;
    int lane = tid & 31, wrow = tid >> 5;
    int j0 = lane * 4, r0 = wrow * 8;

    for (int i = tid; i < 64 * 32; i += 256) {
        int r = i >> 5, c4 = i & 31;
        int nr = min(base + r, NN - 1);
        ((float4*)As)[r * 32 + c4] = ((const float4*)g_x)[(size_t)nr * 32 + c4];
    }
    __syncthreads();

    float acc[8][4];
    float4 bb = *(const float4*)(b1 + j0);
#pragma unroll
    for (int r = 0; r < 8; r++) {
        acc[r][0] = bb.x; acc[r][1] = bb.y; acc[r][2] = bb.z; acc[r][3] = bb.w;
    }
#pragma unroll 2
    for (int k4 = 0; k4 < 32; k4++) {
        const float* wr = w1 + (k4 * 4) * HH + j0;
        float4 w0 = *(const float4*)(wr);
        float4 w1v = *(const float4*)(wr + HH);
        float4 w2v = *(const float4*)(wr + 2 * HH);
        float4 w3v = *(const float4*)(wr + 3 * HH);
#pragma unroll
        for (int r = 0; r < 8; r++) {
            float4 a = *(const float4*)(As + (r0 + r) * HH + k4 * 4);
            acc[r][0] += a.x * w0.x + a.y * w1v.x + a.z * w2v.x + a.w * w3v.x;
            acc[r][1] += a.x * w0.y + a.y * w1v.y + a.z * w2v.y + a.w * w3v.y;
            acc[r][2] += a.x * w0.z + a.y * w1v.z + a.z * w2v.z + a.w * w3v.z;
            acc[r][3] += a.x * w0.w + a.y * w1v.w + a.z * w2v.w + a.w * w3v.w;
        }
    }
    __syncthreads();
#pragma unroll
    for (int r = 0; r < 8; r++) {
        float4 h = make_float4(fmaxf(acc[r][0], 0.f), fmaxf(acc[r][1], 0.f),
                               fmaxf(acc[r][2], 0.f), fmaxf(acc[r][3], 0.f));
        *(float4*)(As + (r0 + r) * HH + j0) = h;
    }
    __syncthreads();

    if (tid < 192) {
        int r = tid / 3, c = tid - r * 3;
        float s = b2[c];
#pragma unroll 4
        for (int k = 0; k < HH; k++) s += As[r * HH + k] * w2[k * 3 + c];
        int nr = base + r;
        if (nr < NN) out[nr * 3 + c] = s;
    }
}

// ============================================================================
extern "C" void kernel_launch(void* const* d_in, const int* in_sizes, int n_in,
                              void* d_out, int out_size) {
    const float* x_in    = (const float*)d_in[0];
    const float* eattr   = (const float*)d_in[1];
    const float* ne_w1   = (const float*)d_in[2];
    const float* ne_b1   = (const float*)d_in[3];
    const float* ne_w2   = (const float*)d_in[4];
    const float* ne_b2   = (const float*)d_in[5];
    const float* ee_w1   = (const float*)d_in[6];
    const float* ee_b1   = (const float*)d_in[7];
    const float* ee_w2   = (const float*)d_in[8];
    const float* ee_b2   = (const float*)d_in[9];
    const float* edge_w1 = (const float*)d_in[10];
    const float* edge_b1 = (const float*)d_in[11];
    const float* edge_w2 = (const float*)d_in[12];
    const float* edge_b2 = (const float*)d_in[13];
    const float* node_w1 = (const float*)d_in[14];
    const float* node_b1 = (const float*)d_in[15];
    const float* node_w2 = (const float*)d_in[16];
    const float* node_b2 = (const float*)d_in[17];
    const float* nd_w1   = (const float*)d_in[18];
    const float* nd_b1   = (const float*)d_in[19];
    const float* nd_w2   = (const float*)d_in[20];
    const float* nd_b2   = (const float*)d_in[21];
    const int*   eidx    = (const int*)d_in[22];
    const int*   rowi    = eidx;
    const int*   coli    = eidx + EE;

    cudaFuncSetAttribute(edge_layer_persist,
                         cudaFuncAttributeMaxDynamicSharedMemorySize, E_SMEM);
    cudaFuncSetAttribute(xsxd_mma,
                         cudaFuncAttributeMaxDynamicSharedMemorySize, G_SMEM);
    cudaFuncSetAttribute(node_layer_mma,
                         cudaFuncAttributeMaxDynamicSharedMemorySize, G_SMEM);
    cudaFuncSetAttribute(encoder_mma<6, 0>,
                         cudaFuncAttributeMaxDynamicSharedMemorySize, G_SMEM);
    cudaFuncSetAttribute(encoder_mma<3, 1>,
                         cudaFuncAttributeMaxDynamicSharedMemorySize, G_SMEM);

    pack_w<<<LL * 64, 256>>>(edge_w1,             0, 3 * 16384);
    pack_w<<<LL * 64, 256>>>(edge_w1 + 16384,     1, 3 * 16384);
    pack_w<<<LL * 64, 256>>>(edge_w1 + 2 * 16384, 2, 3 * 16384);
    pack_w<<<LL * 64, 256>>>(edge_w2,             3, 16384);
    pack_w<<<LL * 64, 256>>>(node_w1,             4, 2 * 16384);
    pack_w<<<LL * 64, 256>>>(node_w1 + 16384,     5, 2 * 16384);
    pack_w<<<LL * 64, 256>>>(node_w2,             6, 16384);
    pack_w<<<64, 256>>>(ne_w2, 7, 16384);
    pack_w<<<64, 256>>>(ee_w2, 8, 16384);

    const int TB_N = (NN + 127) / 128;   // 157
    const int TB_E = (EE + 127) / 128;   // 2344

    encoder_mma<6, 0><<<TB_N, 256, G_SMEM>>>(x_in, ne_w1, ne_b1, ne_b2, NN, TB_N);
    encoder_mma<3, 1><<<NSM, 256, G_SMEM>>>(eattr, ee_w1, ee_b1, ee_b2, EE, TB_E);

    for (int l = 0; l < LL; l++) {
        xsxd_mma<<<TB_N, 256, G_SMEM>>>(l);
        edge_layer_persist<<<NSM, 256, E_SMEM>>>(l, edge_b1 + l * HH,
                                                 edge_b2 + l * HH, rowi, coli,
                                                 TB_E);
        node_layer_mma<<<TB_N, 256, G_SMEM>>>(l, node_b1 + l * HH,
                                              node_b2 + l * HH);
    }

    decoder_kernel<<<(NN + 63) / 64, 256>>>(nd_w1, nd_b1, nd_w2, nd_b2,
                                            (float*)d_out);
}

// round 7
// speedup vs baseline: 1.3223x; 1.0035x over previous
#include <cuda_runtime.h>
#include <cuda_bf16.h>
#include <cstdint>

#define NN 20000
#define EE 300000
#define HH 128
#define LL 8
#define PITCH 272   // smem row pitch bytes (136 bf16) — conflict-free ldmatrix
#define NSM 148

// 128-row-tile smem layout (bytes)
#define A_HI 0
#define A_LO 34816
#define B_HI 69632          // generic kernels: single weight (hi/lo) region
#define G_SMEM 140288
// persistent kernels: two resident weights
#define W1_HI 69632
#define W2_HI 139264
#define E_IDX 208896
#define E_SMEM 209920

// ============================ scratch globals ===============================
__device__ __align__(16) float g_x  [NN * HH];
__device__ __align__(16) float g_xs [NN * HH];
__device__ __align__(16) float g_xd [NN * HH];
__device__ __align__(16) float g_agg[NN * HH];
// edge features, packed bf16 hi/lo (bf16x2 per 2 columns): 64 words per edge
__device__ __align__(16) uint32_t g_ehi[(size_t)EE * 64];
__device__ __align__(16) uint32_t g_elo[(size_t)EE * 64];

// packed weights: per matrix [hi 128x128 | lo 128x128] bf16, TRANSPOSED
__device__ __align__(16) __nv_bfloat16 g_wsrc[LL * 32768];
__device__ __align__(16) __nv_bfloat16 g_wdst[LL * 32768];
__device__ __align__(16) __nv_bfloat16 g_we  [LL * 32768];
__device__ __align__(16) __nv_bfloat16 g_we2 [LL * 32768];
__device__ __align__(16) __nv_bfloat16 g_wnx [LL * 32768];
__device__ __align__(16) __nv_bfloat16 g_wna [LL * 32768];
__device__ __align__(16) __nv_bfloat16 g_wn2 [LL * 32768];
__device__ __align__(16) __nv_bfloat16 g_wne2[32768];
__device__ __align__(16) __nv_bfloat16 g_wee2[32768];

// ============================ helpers =======================================
__device__ __forceinline__ uint32_t smem_u32(const void* p) {
    uint32_t a;
    asm("{ .reg .u64 t; cvta.to.shared.u64 t, %1; cvt.u32.u64 %0, t; }"
        : "=r"(a) : "l"(p));
    return a;
}
__device__ __forceinline__ void ldsm4(uint32_t addr, uint32_t r[4]) {
    asm volatile("ldmatrix.sync.aligned.m8n8.x4.shared.b16 {%0,%1,%2,%3}, [%4];"
                 : "=r"(r[0]), "=r"(r[1]), "=r"(r[2]), "=r"(r[3]) : "r"(addr));
}
__device__ __forceinline__ void mma16816(float c[4], const uint32_t a[4],
                                         const uint32_t* b) {
    asm volatile("mma.sync.aligned.m16n8k16.row.col.f32.bf16.bf16.f32 "
                 "{%0,%1,%2,%3}, {%4,%5,%6,%7}, {%8,%9}, {%0,%1,%2,%3};"
                 : "+f"(c[0]), "+f"(c[1]), "+f"(c[2]), "+f"(c[3])
                 : "r"(a[0]), "r"(a[1]), "r"(a[2]), "r"(a[3]),
                   "r"(b[0]), "r"(b[1]));
}
#define CP16(dst, src) \
    asm volatile("cp.async.cg.shared.global [%0], [%1], 16;" \
                 :: "r"(dst), "l"(src) : "memory")
#define CP_WAIT() \
    asm volatile("cp.async.commit_group;\n\tcp.async.wait_group 0;" ::: "memory")

// packed hi/lo bf16 split: hi = bf16x2(lo-half=a, hi-half=b), lo = residuals
__device__ __forceinline__ void split2(float a, float b, uint32_t& hi, uint32_t& lo) {
    asm("cvt.rn.bf16x2.f32 %0, %1, %2;" : "=r"(hi) : "f"(b), "f"(a));
    float ah = __uint_as_float(hi << 16);
    float bh = __uint_as_float(hi & 0xFFFF0000u);
    asm("cvt.rn.bf16x2.f32 %0, %1, %2;" : "=r"(lo) : "f"(b - bh), "f"(a - ah));
}

// 3-term emulated fp32 GEMM, warp tile 32x64 of a 128x128 output
__device__ __forceinline__ void warp_gemm3(const char* sm, uint32_t b_off,
                                           int wr, int wc, int lid,
                                           float acc[2][8][4]) {
    uint32_t sb = smem_u32(sm);
    uint32_t a_base = sb + A_HI + (uint32_t)(wr * 32 + (lid & 15)) * PITCH +
                      (uint32_t)((lid >> 4) * 8) * 2;
    uint32_t b_base = sb + b_off +
        (uint32_t)(wc * 64 + ((lid >> 4) & 1) * 8 + (lid & 7)) * PITCH +
        (uint32_t)(((lid >> 3) & 1) * 8) * 2;
#pragma unroll
    for (int ks = 0; ks < 8; ks++) {
        uint32_t ko = ks * 32;
        uint32_t Ah[2][4], Al[2][4], Bh[4][4], Bl[4][4];
        ldsm4(a_base + ko, Ah[0]);
        ldsm4(a_base + 16 * PITCH + ko, Ah[1]);
        ldsm4(a_base + 34816 + ko, Al[0]);
        ldsm4(a_base + 34816 + 16 * PITCH + ko, Al[1]);
#pragma unroll
        for (int g = 0; g < 4; g++) {
            ldsm4(b_base + g * 16 * PITCH + ko, Bh[g]);
            ldsm4(b_base + 34816 + g * 16 * PITCH + ko, Bl[g]);
        }
#pragma unroll
        for (int m = 0; m < 2; m++)
#pragma unroll
            for (int g = 0; g < 4; g++)
#pragma unroll
                for (int s = 0; s < 2; s++) {
                    float* c = acc[m][g * 2 + s];
                    mma16816(c, Ah[m], &Bh[g][2 * s]);
                    mma16816(c, Al[m], &Bh[g][2 * s]);
                    mma16816(c, Ah[m], &Bl[g][2 * s]);
                }
    }
}

#define ZACC(acc)                                   \
    _Pragma("unroll") for (int _m = 0; _m < 2; _m++) \
    _Pragma("unroll") for (int _n = 0; _n < 8; _n++) \
    _Pragma("unroll") for (int _q = 0; _q < 4; _q++) acc[_m][_n][_q] = 0.f;

// load [128,128] f32 tile (row-clamped) -> bf16 hi/lo into A region
__device__ __forceinline__ void load_split_tile(const float* __restrict__ src,
                                                int base, int maxr, char* sm) {
    for (int g = threadIdx.x; g < 2048; g += 256) {
        int r = g >> 4, c8 = (g & 15) << 3;
        int rr = min(base + r, maxr - 1);
        const float* p = src + (size_t)rr * HH + c8;
        float4 v0 = *(const float4*)p;
        float4 v1 = *(const float4*)(p + 4);
        uint32_t h0, l0, h1, l1, h2, l2, h3, l3;
        split2(v0.x, v0.y, h0, l0); split2(v0.z, v0.w, h1, l1);
        split2(v1.x, v1.y, h2, l2); split2(v1.z, v1.w, h3, l3);
        char* dst = sm + (size_t)r * PITCH + c8 * 2;
        *(uint4*)(dst + A_HI) = make_uint4(h0, h1, h2, h3);
        *(uint4*)(dst + A_LO) = make_uint4(l0, l1, l2, l3);
    }
}

// copy packed weight matrix (hi 32KB + lo 32KB) into smem at off_hi
__device__ __forceinline__ void copy_w(const __nv_bfloat16* __restrict__ w,
                                       char* sm, uint32_t off_hi) {
    const uint4* s = (const uint4*)w;
    for (int i = threadIdx.x; i < 2048; i += 256) {
        int r = i >> 4, c = i & 15;
        char* dst = sm + off_hi + (size_t)r * PITCH + c * 16;
        *(uint4*)(dst) = s[i];
        *(uint4*)(dst + 34816) = s[i + 2048];
    }
}

// ============================ pack kernel ===================================
__global__ void pack_w(const float* __restrict__ src, int which, int stride) {
    __nv_bfloat16* dst =
        which == 0 ? g_wsrc : which == 1 ? g_wdst : which == 2 ? g_we :
        which == 3 ? g_we2  : which == 4 ? g_wnx  : which == 5 ? g_wna :
        which == 6 ? g_wn2  : which == 7 ? g_wne2 : g_wee2;
    int i = blockIdx.x * 256 + threadIdx.x;
    int m = i >> 14, t = i & 16383;
    int n = t >> 7, k = t & 127;
    float v = src[(size_t)m * stride + k * HH + n];   // transpose
    __nv_bfloat16 h = __float2bfloat16_rn(v);
    __nv_bfloat16 lo = __float2bfloat16_rn(v - __bfloat162float(h));
    __nv_bfloat16* b = dst + (size_t)m * 32768;
    b[t] = h;
    b[t + 16384] = lo;
}

// ================= persistent edge layer (weights resident) =================
__global__ __launch_bounds__(256, 1) void edge_layer_persist(
    int l, const float* __restrict__ b1, const float* __restrict__ b2,
    const int* __restrict__ rowi, const int* __restrict__ coli,
    int ntiles, int store_e) {
    extern __shared__ __align__(16) char sm[];
    uint32_t sb = smem_u32(sm);
    int tid = threadIdx.x, lid = tid & 31, wid = tid >> 5;
    int wr = wid >> 1, wc = wid & 1;
    int* rs = (int*)(sm + E_IDX);
    int* cs = rs + 128;

    copy_w(g_we + (size_t)l * 32768, sm, W1_HI);
    copy_w(g_we2 + (size_t)l * 32768, sm, W2_HI);

    int lq = lid >> 2, lr = (lid & 3) * 2;

    for (int t = blockIdx.x; t < ntiles; t += gridDim.x) {
        int ebase = t * 128;
        __syncthreads();   // previous iter's smem reads done; weights ready

        // A tile: plain byte copy of packed hi/lo edge features (cp.async)
        for (int g = tid; g < 2048; g += 256) {
            int r = g >> 4, cp2 = (g & 15) << 2;   // col-pair index (4 pairs)
            int er = min(ebase + r, EE - 1);
            uint32_t d = sb + (uint32_t)r * PITCH + (uint32_t)cp2 * 4;
            CP16(d + A_HI, g_ehi + (size_t)er * 64 + cp2);
            CP16(d + A_LO, g_elo + (size_t)er * 64 + cp2);
        }
        if (tid < 128) {
            int er = min(ebase + tid, EE - 1);
            rs[tid] = rowi[er];
            cs[tid] = coli[er];
        }
        CP_WAIT();
        __syncthreads();

        float acc[2][8][4];
        ZACC(acc);
        warp_gemm3(sm, W1_HI, wr, wc, lid, acc);
        __syncthreads();

#pragma unroll
        for (int m = 0; m < 2; m++) {
            int rA = wr * 32 + m * 16 + lq, rB = rA + 8;
            const float* xsA = g_xs + (size_t)rs[rA] * HH;
            const float* xdA = g_xd + (size_t)cs[rA] * HH;
            const float* xsB = g_xs + (size_t)rs[rB] * HH;
            const float* xdB = g_xd + (size_t)cs[rB] * HH;
#pragma unroll
            for (int n = 0; n < 8; n++) {
                int col = wc * 64 + n * 8 + lr;
                float2 bv = *(const float2*)(b1 + col);
                float2 sA = *(const float2*)(xsA + col);
                float2 dA = *(const float2*)(xdA + col);
                float2 sB = *(const float2*)(xsB + col);
                float2 dB = *(const float2*)(xdB + col);
                float* c = acc[m][n];
                float h0 = fmaxf(c[0] + bv.x + sA.x + dA.x, 0.f);
                float h1 = fmaxf(c[1] + bv.y + sA.y + dA.y, 0.f);
                float h2 = fmaxf(c[2] + bv.x + sB.x + dB.x, 0.f);
                float h3 = fmaxf(c[3] + bv.y + sB.y + dB.y, 0.f);
                uint32_t hi, lo;
                split2(h0, h1, hi, lo);
                *(uint32_t*)(sm + A_HI + (size_t)rA * PITCH + col * 2) = hi;
                *(uint32_t*)(sm + A_LO + (size_t)rA * PITCH + col * 2) = lo;
                split2(h2, h3, hi, lo);
                *(uint32_t*)(sm + A_HI + (size_t)rB * PITCH + col * 2) = hi;
                *(uint32_t*)(sm + A_LO + (size_t)rB * PITCH + col * 2) = lo;
            }
        }
        __syncthreads();

        ZACC(acc);
        warp_gemm3(sm, W2_HI, wr, wc, lid, acc);

#pragma unroll
        for (int m = 0; m < 2; m++) {
            int rA = wr * 32 + m * 16 + lq, rB = rA + 8;
            int eA = ebase + rA, eB = ebase + rB;
            float* aggA = g_agg + (size_t)rs[rA] * HH;
            float* aggB = g_agg + (size_t)rs[rB] * HH;
#pragma unroll
            for (int n = 0; n < 8; n++) {
                int col = wc * 64 + n * 8 + lr;
                float2 bv = *(const float2*)(b2 + col);
                float* c = acc[m][n];
                if (eA < EE) {
                    float vx = c[0] + bv.x, vy = c[1] + bv.y;
                    if (store_e) {
                        uint32_t hi, lo;
                        split2(vx, vy, hi, lo);
                        g_ehi[(size_t)eA * 64 + (col >> 1)] = hi;
                        g_elo[(size_t)eA * 64 + (col >> 1)] = lo;
                    }
                    asm volatile("red.global.add.v2.f32 [%0], {%1, %2};"
                                 :: "l"(aggA + col), "f"(vx), "f"(vy) : "memory");
                }
                if (eB < EE) {
                    float vx = c[2] + bv.x, vy = c[3] + bv.y;
                    if (store_e) {
                        uint32_t hi, lo;
                        split2(vx, vy, hi, lo);
                        g_ehi[(size_t)eB * 64 + (col >> 1)] = hi;
                        g_elo[(size_t)eB * 64 + (col >> 1)] = lo;
                    }
                    asm volatile("red.global.add.v2.f32 [%0], {%1, %2};"
                                 :: "l"(aggB + col), "f"(vx), "f"(vy) : "memory");
                }
            }
        }
    }
}

// ====== persistent xs/xd projections (both weights resident) + agg zero =====
__global__ __launch_bounds__(256, 1) void xsxd_persist(int l, int ntiles) {
    extern __shared__ __align__(16) char sm[];
    int tid = threadIdx.x, lid = tid & 31, wid = tid >> 5;
    int wr = wid >> 1, wc = wid & 1;

    copy_w(g_wsrc + (size_t)l * 32768, sm, W1_HI);
    copy_w(g_wdst + (size_t)l * 32768, sm, W2_HI);

    int lq = lid >> 2, lr = (lid & 3) * 2;

    for (int t = blockIdx.x; t < ntiles; t += gridDim.x) {
        int base = t * 128;
        __syncthreads();

        for (int i = tid; i < 4096; i += 256) {
            int r = i >> 5, c4 = i & 31;
            if (base + r < NN)
                ((float4*)g_agg)[(size_t)(base + r) * 32 + c4] =
                    make_float4(0.f, 0.f, 0.f, 0.f);
        }
        load_split_tile(g_x, base, NN, sm);
        __syncthreads();

        float acc[2][8][4];
        ZACC(acc);
        warp_gemm3(sm, W1_HI, wr, wc, lid, acc);
#pragma unroll
        for (int m = 0; m < 2; m++) {
            int rA = wr * 32 + m * 16 + lq, rB = rA + 8;
#pragma unroll
            for (int n = 0; n < 8; n++) {
                int col = wc * 64 + n * 8 + lr;
                float* c = acc[m][n];
                if (base + rA < NN)
                    *(float2*)(g_xs + (size_t)(base + rA) * HH + col) =
                        make_float2(c[0], c[1]);
                if (base + rB < NN)
                    *(float2*)(g_xs + (size_t)(base + rB) * HH + col) =
                        make_float2(c[2], c[3]);
            }
        }

        ZACC(acc);
        warp_gemm3(sm, W2_HI, wr, wc, lid, acc);
#pragma unroll
        for (int m = 0; m < 2; m++) {
            int rA = wr * 32 + m * 16 + lq, rB = rA + 8;
#pragma unroll
            for (int n = 0; n < 8; n++) {
                int col = wc * 64 + n * 8 + lr;
                float* c = acc[m][n];
                if (base + rA < NN)
                    *(float2*)(g_xd + (size_t)(base + rA) * HH + col) =
                        make_float2(c[0], c[1]);
                if (base + rB < NN)
                    *(float2*)(g_xd + (size_t)(base + rB) * HH + col) =
                        make_float2(c[2], c[3]);
            }
        }
    }
}

// =========================== node layer =====================================
__global__ __launch_bounds__(256, 1) void node_layer_mma(
    int l, const float* __restrict__ b1, const float* __restrict__ b2) {
    extern __shared__ __align__(16) char sm[];
    int tid = threadIdx.x, lid = tid & 31, wid = tid >> 5;
    int wr = wid >> 1, wc = wid & 1;
    int base = blockIdx.x * 128;

    load_split_tile(g_x, base, NN, sm);
    copy_w(g_wnx + (size_t)l * 32768, sm, B_HI);
    __syncthreads();

    float acc[2][8][4];
    ZACC(acc);
    warp_gemm3(sm, B_HI, wr, wc, lid, acc);
    __syncthreads();

    load_split_tile(g_agg, base, NN, sm);
    copy_w(g_wna + (size_t)l * 32768, sm, B_HI);
    __syncthreads();
    warp_gemm3(sm, B_HI, wr, wc, lid, acc);
    __syncthreads();

    int lq = lid >> 2, lr = (lid & 3) * 2;
#pragma unroll
    for (int m = 0; m < 2; m++) {
        int rA = wr * 32 + m * 16 + lq, rB = rA + 8;
#pragma unroll
        for (int n = 0; n < 8; n++) {
            int col = wc * 64 + n * 8 + lr;
            float2 bv = *(const float2*)(b1 + col);
            float* c = acc[m][n];
            float h0 = fmaxf(c[0] + bv.x, 0.f);
            float h1 = fmaxf(c[1] + bv.y, 0.f);
            float h2 = fmaxf(c[2] + bv.x, 0.f);
            float h3 = fmaxf(c[3] + bv.y, 0.f);
            uint32_t hi, lo;
            split2(h0, h1, hi, lo);
            *(uint32_t*)(sm + A_HI + (size_t)rA * PITCH + col * 2) = hi;
            *(uint32_t*)(sm + A_LO + (size_t)rA * PITCH + col * 2) = lo;
            split2(h2, h3, hi, lo);
            *(uint32_t*)(sm + A_HI + (size_t)rB * PITCH + col * 2) = hi;
            *(uint32_t*)(sm + A_LO + (size_t)rB * PITCH + col * 2) = lo;
        }
    }
    copy_w(g_wn2 + (size_t)l * 32768, sm, B_HI);
    __syncthreads();

    ZACC(acc);
    warp_gemm3(sm, B_HI, wr, wc, lid, acc);

#pragma unroll
    for (int m = 0; m < 2; m++) {
        int rA = wr * 32 + m * 16 + lq, rB = rA + 8;
#pragma unroll
        for (int n = 0; n < 8; n++) {
            int col = wc * 64 + n * 8 + lr;
            float2 bv = *(const float2*)(b2 + col);
            float* c = acc[m][n];
            if (base + rA < NN) {
                float* xp = g_x + (size_t)(base + rA) * HH + col;
                float2 xv = *(float2*)xp;
                *(float2*)xp = make_float2(c[0] + bv.x + xv.x, c[1] + bv.y + xv.y);
            }
            if (base + rB < NN) {
                float* xp = g_x + (size_t)(base + rB) * HH + col;
                float2 xv = *(float2*)xp;
                *(float2*)xp = make_float2(c[2] + bv.x + xv.x, c[3] + bv.y + xv.y);
            }
        }
    }
}

// ==================== encoders (persistent, W resident) =====================
template <int K1, int DST>
__global__ __launch_bounds__(256, 1) void encoder_mma(
    const float* __restrict__ in, const float* __restrict__ w1,
    const float* __restrict__ b1, const float* __restrict__ b2,
    int rows, int ntiles) {
    extern __shared__ __align__(16) char sm[];
    int tid = threadIdx.x, lid = tid & 31, wid = tid >> 5;
    int wr = wid >> 1, wc = wid & 1;

    copy_w(DST ? g_wee2 : g_wne2, sm, B_HI);
    int lq = lid >> 2, lr = (lid & 3) * 2;

    for (int t = blockIdx.x; t < ntiles; t += gridDim.x) {
        int base = t * 128;
        __syncthreads();
        for (int g = tid; g < 2048; g += 256) {
            int r = g >> 4, c8 = (g & 15) << 3;
            int rr = min(base + r, rows - 1);
            float vin[K1];
#pragma unroll
            for (int k = 0; k < K1; k++) vin[k] = in[(size_t)rr * K1 + k];
            float h[8];
#pragma unroll
            for (int c = 0; c < 8; c++) {
                int cc = c8 + c;
                float s = b1[cc];
#pragma unroll
                for (int k = 0; k < K1; k++) s += vin[k] * w1[k * HH + cc];
                h[c] = fmaxf(s, 0.f);
            }
            uint32_t hv[4], lv[4];
            split2(h[0], h[1], hv[0], lv[0]);
            split2(h[2], h[3], hv[1], lv[1]);
            split2(h[4], h[5], hv[2], lv[2]);
            split2(h[6], h[7], hv[3], lv[3]);
            char* dst = sm + (size_t)r * PITCH + c8 * 2;
            *(uint4*)(dst + A_HI) = make_uint4(hv[0], hv[1], hv[2], hv[3]);
            *(uint4*)(dst + A_LO) = make_uint4(lv[0], lv[1], lv[2], lv[3]);
        }
        __syncthreads();

        float acc[2][8][4];
        ZACC(acc);
        warp_gemm3(sm, B_HI, wr, wc, lid, acc);

#pragma unroll
        for (int m = 0; m < 2; m++) {
            int rA = wr * 32 + m * 16 + lq, rB = rA + 8;
#pragma unroll
            for (int n = 0; n < 8; n++) {
                int col = wc * 64 + n * 8 + lr;
                float2 bv = *(const float2*)(b2 + col);
                float* c = acc[m][n];
                if (DST) {
                    uint32_t hi, lo;
                    if (base + rA < rows) {
                        split2(c[0] + bv.x, c[1] + bv.y, hi, lo);
                        g_ehi[(size_t)(base + rA) * 64 + (col >> 1)] = hi;
                        g_elo[(size_t)(base + rA) * 64 + (col >> 1)] = lo;
                    }
                    if (base + rB < rows) {
                        split2(c[2] + bv.x, c[3] + bv.y, hi, lo);
                        g_ehi[(size_t)(base + rB) * 64 + (col >> 1)] = hi;
                        g_elo[(size_t)(base + rB) * 64 + (col >> 1)] = lo;
                    }
                } else {
                    if (base + rA < rows)
                        *(float2*)(g_x + (size_t)(base + rA) * HH + col) =
                            make_float2(c[0] + bv.x, c[1] + bv.y);
                    if (base + rB < rows)
                        *(float2*)(g_x + (size_t)(base + rB) * HH + col) =
                            make_float2(c[2] + bv.x, c[3] + bv.y);
                }
            }
        }
    }
}

// ============================ decoder (scalar) ==============================
__global__ __launch_bounds__(256) void decoder_kernel(
    const float* __restrict__ w1, const float* __restrict__ b1,
    const float* __restrict__ w2, const float* __restrict__ b2,
    float* __restrict__ out) {
    __shared__ __align__(16) float As[64 * HH];
    int tid = threadIdx.x;
    int base = blockIdx.x * 64;
    int lane = tid & 31, wrow = tid >> 5;
    int j0 = lane * 4, r0 = wrow * 8;

    for (int i = tid; i < 64 * 32; i += 256) {
        int r = i >> 5, c4 = i & 31;
        int nr = min(base + r, NN - 1);
        ((float4*)As)[r * 32 + c4] = ((const float4*)g_x)[(size_t)nr * 32 + c4];
    }
    __syncthreads();

    float acc[8][4];
    float4 bb = *(const float4*)(b1 + j0);
#pragma unroll
    for (int r = 0; r < 8; r++) {
        acc[r][0] = bb.x; acc[r][1] = bb.y; acc[r][2] = bb.z; acc[r][3] = bb.w;
    }
#pragma unroll 2
    for (int k4 = 0; k4 < 32; k4++) {
        const float* wr = w1 + (k4 * 4) * HH + j0;
        float4 w0 = *(const float4*)(wr);
        float4 w1v = *(const float4*)(wr + HH);
        float4 w2v = *(const float4*)(wr + 2 * HH);
        float4 w3v = *(const float4*)(wr + 3 * HH);
#pragma unroll
        for (int r = 0; r < 8; r++) {
            float4 a = *(const float4*)(As + (r0 + r) * HH + k4 * 4);
            acc[r][0] += a.x * w0.x + a.y * w1v.x + a.z * w2v.x + a.w * w3v.x;
            acc[r][1] += a.x * w0.y + a.y * w1v.y + a.z * w2v.y + a.w * w3v.y;
            acc[r][2] += a.x * w0.z + a.y * w1v.z + a.z * w2v.z + a.w * w3v.z;
            acc[r][3] += a.x * w0.w + a.y * w1v.w + a.z * w2v.w + a.w * w3v.w;
        }
    }
    __syncthreads();
#pragma unroll
    for (int r = 0; r < 8; r++) {
        float4 h = make_float4(fmaxf(acc[r][0], 0.f), fmaxf(acc[r][1], 0.f),
                               fmaxf(acc[r][2], 0.f), fmaxf(acc[r][3], 0.f));
        *(float4*)(As + (r0 + r) * HH + j0) = h;
    }
    __syncthreads();

    if (tid < 192) {
        int r = tid / 3, c = tid - r * 3;
        float s = b2[c];
#pragma unroll 4
        for (int k = 0; k < HH; k++) s += As[r * HH + k] * w2[k * 3 + c];
        int nr = base + r;
        if (nr < NN) out[nr * 3 + c] = s;
    }
}

// ============================================================================
extern "C" void kernel_launch(void* const* d_in, const int* in_sizes, int n_in,
                              void* d_out, int out_size) {
    const float* x_in    = (const float*)d_in[0];
    const float* eattr   = (const float*)d_in[1];
    const float* ne_w1   = (const float*)d_in[2];
    const float* ne_b1   = (const float*)d_in[3];
    const float* ne_w2   = (const float*)d_in[4];
    const float* ne_b2   = (const float*)d_in[5];
    const float* ee_w1   = (const float*)d_in[6];
    const float* ee_b1   = (const float*)d_in[7];
    const float* ee_w2   = (const float*)d_in[8];
    const float* ee_b2   = (const float*)d_in[9];
    const float* edge_w1 = (const float*)d_in[10];
    const float* edge_b1 = (const float*)d_in[11];
    const float* edge_w2 = (const float*)d_in[12];
    const float* edge_b2 = (const float*)d_in[13];
    const float* node_w1 = (const float*)d_in[14];
    const float* node_b1 = (const float*)d_in[15];
    const float* node_w2 = (const float*)d_in[16];
    const float* node_b2 = (const float*)d_in[17];
    const float* nd_w1   = (const float*)d_in[18];
    const float* nd_b1   = (const float*)d_in[19];
    const float* nd_w2   = (const float*)d_in[20];
    const float* nd_b2   = (const float*)d_in[21];
    const int*   eidx    = (const int*)d_in[22];
    const int*   rowi    = eidx;
    const int*   coli    = eidx + EE;

    cudaFuncSetAttribute(edge_layer_persist,
                         cudaFuncAttributeMaxDynamicSharedMemorySize, E_SMEM);
    cudaFuncSetAttribute(xsxd_persist,
                         cudaFuncAttributeMaxDynamicSharedMemorySize, E_SMEM);
    cudaFuncSetAttribute(node_layer_mma,
                         cudaFuncAttributeMaxDynamicSharedMemorySize, G_SMEM);
    cudaFuncSetAttribute(encoder_mma<6, 0>,
                         cudaFuncAttributeMaxDynamicSharedMemorySize, G_SMEM);
    cudaFuncSetAttribute(encoder_mma<3, 1>,
                         cudaFuncAttributeMaxDynamicSharedMemorySize, G_SMEM);

    pack_w<<<LL * 64, 256>>>(edge_w1,             0, 3 * 16384);
    pack_w<<<LL * 64, 256>>>(edge_w1 + 16384,     1, 3 * 16384);
    pack_w<<<LL * 64, 256>>>(edge_w1 + 2 * 16384, 2, 3 * 16384);
    pack_w<<<LL * 64, 256>>>(edge_w2,             3, 16384);
    pack_w<<<LL * 64, 256>>>(node_w1,             4, 2 * 16384);
    pack_w<<<LL * 64, 256>>>(node_w1 + 16384,     5, 2 * 16384);
    pack_w<<<LL * 64, 256>>>(node_w2,             6, 16384);
    pack_w<<<64, 256>>>(ne_w2, 7, 16384);
    pack_w<<<64, 256>>>(ee_w2, 8, 16384);

    const int TB_N = (NN + 127) / 128;   // 157
    const int TB_E = (EE + 127) / 128;   // 2344

    encoder_mma<6, 0><<<TB_N, 256, G_SMEM>>>(x_in, ne_w1, ne_b1, ne_b2, NN, TB_N);
    encoder_mma<3, 1><<<NSM, 256, G_SMEM>>>(eattr, ee_w1, ee_b1, ee_b2, EE, TB_E);

    for (int l = 0; l < LL; l++) {
        xsxd_persist<<<NSM, 256, E_SMEM>>>(l, TB_N);
        edge_layer_persist<<<NSM, 256, E_SMEM>>>(l, edge_b1 + l * HH,
                                                 edge_b2 + l * HH, rowi, coli,
                                                 TB_E, l < LL - 1 ? 1 : 0);
        node_layer_mma<<<TB_N, 256, G_SMEM>>>(l, node_b1 + l * HH,
                                              node_b2 + l * HH);
    }

    decoder_kernel<<<(NN + 63) / 64, 256>>>(nd_w1, nd_b1, nd_w2, nd_b2,
                                            (float*)d_out);
}